// round 7
// baseline (speedup 1.0000x reference)
#include <cuda_runtime.h>
#include <cuda_fp16.h>
#include <cstdint>

#define Bn 256
#define Qn 16
#define Sn 512
#define Mn 8
#define Dn 128
#define NT 256
#define TILE 64
#define NCHUNK 8
#define PPITCH 520
#define CGP 132

typedef unsigned long long ull;

// ---- shared memory layout (float offsets) ----
#define OFF_QT   0          // qT[128][16] fp32 (cg scores only)
#define OFF_P    2048       // p[16][520]
#define OFF_W    10368      // w[512]
#define OFF_OUT  10880      // out [q][128]
#define OFF_KBAR 12928      // kbar [q][128]
#define OFF_OCG  14976      // cg out [q][128]
#define OFF_KBCG 17024      // cg kbar [q][128]
#define OFF_KCG  19072      // kcg[8][132]
#define OFF_VCG  20128      // vcg[8][132]
#define OFF_PCG  21184      // p_cg[16][8]
#define OFF_WCG  21312      // w_cg[8]
#define OFF_RED  21320      // 8 warps * 4
#define OFF_K32  21376      // [64][129] fp32 stage (phase B)
#define OFF_V32  29632      // [64][129] fp32 stage (phase B) -> 37888
// ---- byte offsets for fp16 tiles ----
// phase A (aliases phase-B regions; phases time-separated):
#define OFF_QHB  (29632*4)  // Q fp16 hi [16 q][272B rows]  (inside V32 region)
#define OFF_QLB  (30720*4)
#define OFF_KSHB (37888*4)  // K fp16 hi [128 s][272B rows]
#define OFF_KSLB (46592*4)
// phase B tiles [128 d][64 s], 128B rows, swizzled:
#define OFF_VHB  (37888*4)
#define OFF_VLB  (41984*4)
#define OFF_WKHB (46080*4)
#define OFF_WKLB (50176*4)
#define OFF_PHB  (54272*4)  // p   [16 q][64 s]
#define OFF_PLB  (54784*4)
#define OFF_PPHB (55296*4)  // p' = p/w
#define OFF_PPLB (55808*4)
#define SMEM_FLOATS 56320   // 225280 bytes

__device__ float g_losses[Bn];

__device__ __forceinline__ float clip50(float x) {
    return fminf(fmaxf(x, -50.0f), 50.0f);
}
__device__ __forceinline__ ull dup2(float x) {
    ull r; asm("mov.b64 %0, {%1, %1};" : "=l"(r) : "f"(x)); return r;
}
__device__ __forceinline__ ull pack2(float x, float y) {
    ull r; asm("mov.b64 %0, {%1, %2};" : "=l"(r) : "f"(x), "f"(y)); return r;
}
__device__ __forceinline__ ull fma2(ull a, ull b, ull c) {
    ull d; asm("fma.rn.f32x2 %0, %1, %2, %3;" : "=l"(d) : "l"(a), "l"(b), "l"(c)); return d;
}
__device__ __forceinline__ float2 unpack2(ull p) {
    float2 f; asm("mov.b64 {%0, %1}, %2;" : "=f"(f.x), "=f"(f.y) : "l"(p)); return f;
}
__device__ __forceinline__ uint32_t smem_u32(const void* p) {
    uint32_t a;
    asm("{ .reg .u64 t; cvta.to.shared.u64 t, %1; cvt.u32.u64 %0, t; }" : "=r"(a) : "l"(p));
    return a;
}
// split (f0,f1) -> fp16x2 hi (f0 low half) + fp16x2 residual
__device__ __forceinline__ void split2h(float f0, float f1, uint32_t& hi, uint32_t& lo) {
    __half2 h = __floats2half2_rn(f0, f1);
    float2 hf = __half22float2(h);
    __half2 l = __floats2half2_rn(f0 - hf.x, f1 - hf.y);
    hi = *(uint32_t*)&h;
    lo = *(uint32_t*)&l;
}
__device__ __forceinline__ uint32_t swz(uint32_t off) { return off ^ ((off >> 3) & 0x70); }

__device__ __forceinline__ void ldsm4(uint32_t* r, uint32_t a) {
    asm volatile("ldmatrix.sync.aligned.m8n8.x4.shared.b16 {%0,%1,%2,%3}, [%4];"
                 : "=r"(r[0]), "=r"(r[1]), "=r"(r[2]), "=r"(r[3]) : "r"(a));
}
__device__ __forceinline__ void mma16816(float* d, const uint32_t* a, uint32_t b0, uint32_t b1) {
    asm volatile("mma.sync.aligned.m16n8k16.row.col.f32.f16.f16.f32 "
                 "{%0,%1,%2,%3}, {%4,%5,%6,%7}, {%8,%9}, {%0,%1,%2,%3};"
                 : "+f"(d[0]), "+f"(d[1]), "+f"(d[2]), "+f"(d[3])
                 : "r"(a[0]), "r"(a[1]), "r"(a[2]), "r"(a[3]), "r"(b0), "r"(b1));
}
// 3-combo split-precision accumulate: acc += (Ah+Al)*(Bh+Bl) minus ll term
#define MMA3(acc, ah, al, bh0, bh1, bl0, bl1) do { \
    mma16816(acc, ah, bh0, bh1); \
    mma16816(acc, ah, bl0, bl1); \
    mma16816(acc, al, bh0, bh1); } while (0)

__global__ void __launch_bounds__(NT, 1)
fml_kernel(const float* __restrict__ gq, const float* __restrict__ gk,
           const float* __restrict__ gv, const float* __restrict__ gkcg,
           const float* __restrict__ gvcg)
{
    extern __shared__ float sm[];
    char* smc = (char*)sm;
    const int b   = blockIdx.x;
    const int tid = threadIdx.x;
    const int wid = tid >> 5, lane = tid & 31;
    const float scale = 0.088388347648318447f;
    const uint32_t smb = smem_u32(sm);

    // ldmatrix lane geometry (same as verified round-6 code)
    const int grp = lane >> 3, li = lane & 7;
    const int arow = (grp & 1) * 8 + li;
    const int akc  = (grp >> 1) * 8;
    const int brow = (grp >> 1) * 8 + li;
    const int bkc  = (grp & 1) * 8;

    // ---- load qT fp32, stage Q fp16 tiles, load cg tensors ----
    const float* qb = gq + (size_t)b * Qn * Dn;
    for (int i = tid; i < Qn * Dn; i += NT) {
        int qq = i >> 7, d = i & 127;
        sm[OFF_QT + d * 16 + qq] = qb[i];
    }
    {   // Q fp16 hi/lo [q][272B rows]
        int q = tid >> 4, dblk = tid & 15;
        float4 f0 = *(const float4*)(qb + q * Dn + dblk * 8);
        float4 f1 = *(const float4*)(qb + q * Dn + dblk * 8 + 4);
        uint32_t h[4], l[4];
        split2h(f0.x, f0.y, h[0], l[0]); split2h(f0.z, f0.w, h[1], l[1]);
        split2h(f1.x, f1.y, h[2], l[2]); split2h(f1.z, f1.w, h[3], l[3]);
        uint32_t off = q * 272 + dblk * 16;
        *(uint4*)(smc + OFF_QHB + off) = make_uint4(h[0], h[1], h[2], h[3]);
        *(uint4*)(smc + OFF_QLB + off) = make_uint4(l[0], l[1], l[2], l[3]);
    }
    const float* kcb = gkcg + (size_t)b * Mn * Dn;
    const float* vcb = gvcg + (size_t)b * Mn * Dn;
    for (int i = tid; i < Mn * Dn; i += NT) {
        int j = i >> 7, d = i & 127;
        sm[OFF_KCG + j * CGP + d] = kcb[i];
        sm[OFF_VCG + j * CGP + d] = vcb[i];
    }
    __syncthreads();

    // ---- cg scores / softmax / w_cg / out / kbar (exact SIMT) ----
    if (tid < Qn * Mn) {
        int qq = tid >> 3, j = tid & 7;
        float acc = 0.f;
        #pragma unroll 8
        for (int d = 0; d < Dn; ++d)
            acc = fmaf(sm[OFF_QT + d * 16 + qq], sm[OFF_KCG + j * CGP + d], acc);
        sm[OFF_PCG + qq * Mn + j] = acc * scale;
    }
    __syncthreads();
    if (tid < Qn) {
        float m = -1e30f;
        #pragma unroll
        for (int j = 0; j < Mn; ++j) m = fmaxf(m, sm[OFF_PCG + tid * Mn + j]);
        float ss = 0.f;
        #pragma unroll
        for (int j = 0; j < Mn; ++j) {
            float e = __expf(sm[OFF_PCG + tid * Mn + j] - m);
            sm[OFF_PCG + tid * Mn + j] = e; ss += e;
        }
        float inv = 1.f / ss;
        #pragma unroll
        for (int j = 0; j < Mn; ++j) sm[OFF_PCG + tid * Mn + j] *= inv;
    }
    __syncthreads();
    if (tid < Mn) {
        float a = 0.f;
        #pragma unroll
        for (int qq = 0; qq < Qn; ++qq) a += sm[OFF_PCG + qq * Mn + tid];
        sm[OFF_WCG + tid] = a;
    }
    {
        int qq = tid >> 4, dblk = tid & 15;
        ull o2[4], kb2[4];
        #pragma unroll
        for (int i = 0; i < 4; ++i) { o2[i] = 0ull; kb2[i] = 0ull; }
        #pragma unroll
        for (int j = 0; j < Mn; ++j) {
            ull pc2 = dup2(sm[OFF_PCG + qq * Mn + j]);
            ulonglong2 vA = *(const ulonglong2*)&sm[OFF_VCG + j * CGP + dblk * 8];
            ulonglong2 vB = *(const ulonglong2*)&sm[OFF_VCG + j * CGP + dblk * 8 + 4];
            ulonglong2 kA = *(const ulonglong2*)&sm[OFF_KCG + j * CGP + dblk * 8];
            ulonglong2 kB = *(const ulonglong2*)&sm[OFF_KCG + j * CGP + dblk * 8 + 4];
            o2[0]  = fma2(pc2, vA.x, o2[0]);  o2[1]  = fma2(pc2, vA.y, o2[1]);
            o2[2]  = fma2(pc2, vB.x, o2[2]);  o2[3]  = fma2(pc2, vB.y, o2[3]);
            kb2[0] = fma2(pc2, kA.x, kb2[0]); kb2[1] = fma2(pc2, kA.y, kb2[1]);
            kb2[2] = fma2(pc2, kB.x, kb2[2]); kb2[3] = fma2(pc2, kB.y, kb2[3]);
        }
        *(ulonglong2*)&sm[OFF_OCG  + qq * Dn + dblk * 8]     = make_ulonglong2(o2[0], o2[1]);
        *(ulonglong2*)&sm[OFF_OCG  + qq * Dn + dblk * 8 + 4] = make_ulonglong2(o2[2], o2[3]);
        *(ulonglong2*)&sm[OFF_KBCG + qq * Dn + dblk * 8]     = make_ulonglong2(kb2[0], kb2[1]);
        *(ulonglong2*)&sm[OFF_KBCG + qq * Dn + dblk * 8 + 4] = make_ulonglong2(kb2[2], kb2[3]);
    }
    __syncthreads();

    // ---- PHASE A: dense scores via HMMA (double-chunks of 128 s) ----
    const float* kbase = gk + (size_t)b * Sn * Dn;
    const float* vbase = gv + (size_t)b * Sn * Dn;
    const int r  = lane >> 2;
    const int cq = (lane & 3) * 2;
    for (int dc = 0; dc < 4; ++dc) {
        // stage K[s][d] fp16 hi/lo directly from gmem (no transpose)
        #pragma unroll
        for (int it = 0; it < 8; ++it) {
            int idx = tid + it * NT;            // [0,2048): 128 s x 16 dblk
            int s = idx >> 4, dblk = idx & 15;
            const float* src = kbase + (size_t)(dc * 128 + s) * Dn + dblk * 8;
            float4 f0 = *(const float4*)src;
            float4 f1 = *(const float4*)(src + 4);
            uint32_t h[4], l[4];
            split2h(f0.x, f0.y, h[0], l[0]); split2h(f0.z, f0.w, h[1], l[1]);
            split2h(f1.x, f1.y, h[2], l[2]); split2h(f1.z, f1.w, h[3], l[3]);
            uint32_t off = s * 272 + dblk * 16;
            *(uint4*)(smc + OFF_KSHB + off) = make_uint4(h[0], h[1], h[2], h[3]);
            *(uint4*)(smc + OFF_KSLB + off) = make_uint4(l[0], l[1], l[2], l[3]);
        }
        __syncthreads();
        // warp wid owns s rows [wid*16, wid*16+16) of this double-chunk
        float accS[2][4];
        #pragma unroll
        for (int n = 0; n < 2; ++n)
            #pragma unroll
            for (int e = 0; e < 4; ++e) accS[n][e] = 0.f;
        #pragma unroll
        for (int k = 0; k < 8; ++k) {
            uint32_t kh[4], kl[4], qh[4], ql[4];
            uint32_t aoff = (wid * 16 + arow) * 272 + (k * 16 + akc) * 2;
            ldsm4(kh, smb + OFF_KSHB + aoff);
            ldsm4(kl, smb + OFF_KSLB + aoff);
            uint32_t boff = brow * 272 + (k * 16 + bkc) * 2;
            ldsm4(qh, smb + OFF_QHB + boff);
            ldsm4(ql, smb + OFF_QLB + boff);
            MMA3(accS[0], kh, kl, qh[0], qh[1], ql[0], ql[1]);
            MMA3(accS[1], kh, kl, qh[2], qh[3], ql[2], ql[3]);
        }
        int sb = dc * 128 + wid * 16;
        #pragma unroll
        for (int n = 0; n < 2; ++n) {
            int q = n * 8 + cq;
            sm[OFF_P + q * PPITCH + sb + r]           = accS[n][0] * scale;
            sm[OFF_P + (q + 1) * PPITCH + sb + r]     = accS[n][1] * scale;
            sm[OFF_P + q * PPITCH + sb + r + 8]       = accS[n][2] * scale;
            sm[OFF_P + (q + 1) * PPITCH + sb + r + 8] = accS[n][3] * scale;
        }
        __syncthreads();
    }

    // ---- softmax rows + w ----
    #pragma unroll
    for (int rr = 0; rr < 2; ++rr) {
        int qq = wid + rr * 8;
        float* row = &sm[OFF_P + qq * PPITCH];
        float m = -1e30f;
        #pragma unroll
        for (int i = 0; i < 16; ++i) m = fmaxf(m, row[lane + 32 * i]);
        #pragma unroll
        for (int o = 16; o > 0; o >>= 1) m = fmaxf(m, __shfl_xor_sync(0xffffffffu, m, o));
        float ss = 0.f;
        float ev[16];
        #pragma unroll
        for (int i = 0; i < 16; ++i) { ev[i] = __expf(row[lane + 32 * i] - m); ss += ev[i]; }
        #pragma unroll
        for (int o = 16; o > 0; o >>= 1) ss += __shfl_xor_sync(0xffffffffu, ss, o);
        float inv = 1.f / ss;
        #pragma unroll
        for (int i = 0; i < 16; ++i) row[lane + 32 * i] = ev[i] * inv;
    }
    __syncthreads();
    for (int s = tid; s < Sn; s += NT) {
        float a = 0.f;
        #pragma unroll
        for (int qq = 0; qq < Qn; ++qq) a += sm[OFF_P + qq * PPITCH + s];
        sm[OFF_W + s] = a;
    }
    __syncthreads();

    // ---- PHASE B: J1 / out / kbar via HMMA, warp grid 4m x 2n ----
    const int mi = wid & 3;     // 32 d-rows: mi*32
    const int nj = wid >> 2;    // 64 n-cols: nj*64
    float accJ[16][4];          // [mt*8 + b8][e]
    float accO[4][4];           // nj==0: out ; nj==1: kbar   [mt*2+nb][e]
    #pragma unroll
    for (int t = 0; t < 16; ++t)
        #pragma unroll
        for (int e = 0; e < 4; ++e) accJ[t][e] = 0.f;
    #pragma unroll
    for (int t = 0; t < 4; ++t)
        #pragma unroll
        for (int e = 0; e < 4; ++e) accO[t][e] = 0.f;

    for (int c = 0; c < NCHUNK; ++c) {
        const int s0 = c * TILE;
        // stage K & V fp32
        #pragma unroll
        for (int it = 0; it < 8; ++it) {
            int fidx = tid + it * NT;
            int row = fidx >> 5, c4 = fidx & 31;
            float4 kv = ((const float4*)(kbase + (size_t)s0 * Dn))[fidx];
            float4 vv = ((const float4*)(vbase + (size_t)s0 * Dn))[fidx];
            float* dk = &sm[OFF_K32 + row * 129 + c4 * 4];
            float* dv = &sm[OFF_V32 + row * 129 + c4 * 4];
            dk[0] = kv.x; dk[1] = kv.y; dk[2] = kv.z; dk[3] = kv.w;
            dv[0] = vv.x; dv[1] = vv.y; dv[2] = vv.z; dv[3] = vv.w;
        }
        __syncthreads();
        // convert: wK -> WKH/WKL, V -> VH/VL  (transpose to [d][s], swizzled)
        {
            float w0 = sm[OFF_W + s0 + 2 * lane];
            float w1 = sm[OFF_W + s0 + 2 * lane + 1];
            #pragma unroll
            for (int rr = 0; rr < 16; ++rr) {
                int d = wid * 16 + rr;
                uint32_t sw = swz((uint32_t)(d * 128 + lane * 4));
                float ka = sm[OFF_K32 + (2 * lane) * 129 + d];
                float kb = sm[OFF_K32 + (2 * lane + 1) * 129 + d];
                uint32_t hi, lo;
                split2h(ka * w0, kb * w1, hi, lo);
                *(uint32_t*)(smc + OFF_WKHB + sw) = hi;
                *(uint32_t*)(smc + OFF_WKLB + sw) = lo;
                float va = sm[OFF_V32 + (2 * lane) * 129 + d];
                float vb = sm[OFF_V32 + (2 * lane + 1) * 129 + d];
                split2h(va, vb, hi, lo);
                *(uint32_t*)(smc + OFF_VHB + sw) = hi;
                *(uint32_t*)(smc + OFF_VLB + sw) = lo;
            }
            // p and p' = p/w
            float wi0 = (w0 > 0.f) ? __fdividef(1.f, w0) : 0.f;
            float wi1 = (w1 > 0.f) ? __fdividef(1.f, w1) : 0.f;
            #pragma unroll
            for (int rr = 0; rr < 2; ++rr) {
                int qq = wid * 2 + rr;
                float p0 = sm[OFF_P + qq * PPITCH + s0 + 2 * lane];
                float p1 = sm[OFF_P + qq * PPITCH + s0 + 2 * lane + 1];
                uint32_t sw = swz((uint32_t)(qq * 128 + lane * 4));
                uint32_t hi, lo;
                split2h(p0, p1, hi, lo);
                *(uint32_t*)(smc + OFF_PHB + sw) = hi;
                *(uint32_t*)(smc + OFF_PLB + sw) = lo;
                split2h(p0 * wi0, p1 * wi1, hi, lo);
                *(uint32_t*)(smc + OFF_PPHB + sw) = hi;
                *(uint32_t*)(smc + OFF_PPLB + sw) = lo;
            }
        }
        __syncthreads();

        // MMAs
        #pragma unroll
        for (int k = 0; k < 4; ++k) {
            uint32_t a0h[4], a0l[4], a1h[4], a1l[4];
            uint32_t aoff0 = swz((uint32_t)((mi * 32 + arow) * 128 + (k * 16 + akc) * 2));
            uint32_t aoff1 = swz((uint32_t)((mi * 32 + 16 + arow) * 128 + (k * 16 + akc) * 2));
            ldsm4(a0h, smb + OFF_VHB + aoff0); ldsm4(a0l, smb + OFF_VLB + aoff0);
            ldsm4(a1h, smb + OFF_VHB + aoff1); ldsm4(a1l, smb + OFF_VLB + aoff1);
            #pragma unroll
            for (int u = 0; u < 4; ++u) {
                uint32_t bh[4], bl[4];
                uint32_t boff = swz((uint32_t)((nj * 64 + u * 16 + brow) * 128 + (k * 16 + bkc) * 2));
                ldsm4(bh, smb + OFF_WKHB + boff);
                ldsm4(bl, smb + OFF_WKLB + boff);
                MMA3(accJ[u * 2],     a0h, a0l, bh[0], bh[1], bl[0], bl[1]);
                MMA3(accJ[u * 2 + 1], a0h, a0l, bh[2], bh[3], bl[2], bl[3]);
                MMA3(accJ[8 + u * 2],     a1h, a1l, bh[0], bh[1], bl[0], bl[1]);
                MMA3(accJ[8 + u * 2 + 1], a1h, a1l, bh[2], bh[3], bl[2], bl[3]);
            }
            uint32_t poff = swz((uint32_t)(brow * 128 + (k * 16 + bkc) * 2));
            if (nj == 0) {
                uint32_t ph[4], pl[4];
                ldsm4(ph, smb + OFF_PHB + poff);
                ldsm4(pl, smb + OFF_PLB + poff);
                MMA3(accO[0], a0h, a0l, ph[0], ph[1], pl[0], pl[1]);
                MMA3(accO[1], a0h, a0l, ph[2], ph[3], pl[2], pl[3]);
                MMA3(accO[2], a1h, a1l, ph[0], ph[1], pl[0], pl[1]);
                MMA3(accO[3], a1h, a1l, ph[2], ph[3], pl[2], pl[3]);
            } else {
                uint32_t w0h[4], w0l[4], w1h[4], w1l[4], pph[4], ppl[4];
                ldsm4(w0h, smb + OFF_WKHB + aoff0); ldsm4(w0l, smb + OFF_WKLB + aoff0);
                ldsm4(w1h, smb + OFF_WKHB + aoff1); ldsm4(w1l, smb + OFF_WKLB + aoff1);
                ldsm4(pph, smb + OFF_PPHB + poff);
                ldsm4(ppl, smb + OFF_PPLB + poff);
                MMA3(accO[0], w0h, w0l, pph[0], pph[1], ppl[0], ppl[1]);
                MMA3(accO[1], w0h, w0l, pph[2], pph[3], ppl[2], ppl[3]);
                MMA3(accO[2], w1h, w1l, pph[0], pph[1], ppl[0], ppl[1]);
                MMA3(accO[3], w1h, w1l, pph[2], pph[3], ppl[2], ppl[3]);
            }
        }
        __syncthreads();
    }

    // ---- write out^T (nj==0) / kbar^T (nj==1) to smem [q][d] ----
    {
        int base = (nj == 0) ? OFF_OUT : OFF_KBAR;
        #pragma unroll
        for (int mt = 0; mt < 2; ++mt)
            #pragma unroll
            for (int nb = 0; nb < 2; ++nb) {
                int q = nb * 8 + cq;
                int d = mi * 32 + mt * 16 + r;
                sm[base + q * Dn + d]           = accO[mt * 2 + nb][0];
                sm[base + (q + 1) * Dn + d]     = accO[mt * 2 + nb][1];
                sm[base + q * Dn + d + 8]       = accO[mt * 2 + nb][2];
                sm[base + (q + 1) * Dn + d + 8] = accO[mt * 2 + nb][3];
            }
    }
    __syncthreads();

    // ---- epilogue: J2 + cg jacobian + clip + cosine ----
    float dd = 0.f, ccv = 0.f, dc2 = 0.f;
    #pragma unroll
    for (int mt = 0; mt < 2; ++mt) {
        int dr0 = mi * 32 + mt * 16 + r, dr1 = dr0 + 8;
        float o0a[16], o1a[16], c0a[16], c1a[16], vc0[8], vc1[8];
        #pragma unroll
        for (int q = 0; q < 16; ++q) {
            o0a[q] = sm[OFF_OUT + q * Dn + dr0];
            o1a[q] = sm[OFF_OUT + q * Dn + dr1];
            c0a[q] = sm[OFF_OCG + q * Dn + dr0];
            c1a[q] = sm[OFF_OCG + q * Dn + dr1];
        }
        #pragma unroll
        for (int j = 0; j < 8; ++j) {
            float wc = sm[OFF_WCG + j];
            vc0[j] = wc * sm[OFF_VCG + j * CGP + dr0];
            vc1[j] = wc * sm[OFF_VCG + j * CGP + dr1];
        }
        #pragma unroll
        for (int b8 = 0; b8 < 8; ++b8) {
            int colb = nj * 64 + b8 * 8 + cq;
            ull jd0 = pack2(accJ[mt * 8 + b8][0], accJ[mt * 8 + b8][1]);
            ull jd1 = pack2(accJ[mt * 8 + b8][2], accJ[mt * 8 + b8][3]);
            ull jc0 = 0ull, jc1 = 0ull;
            #pragma unroll
            for (int q = 0; q < 16; ++q) {
                ull kbp = *(const ull*)&sm[OFF_KBAR + q * Dn + colb];
                jd0 = fma2(dup2(-o0a[q]), kbp, jd0);
                jd1 = fma2(dup2(-o1a[q]), kbp, jd1);
            }
            #pragma unroll
            for (int j = 0; j < 8; ++j) {
                ull kcp = *(const ull*)&sm[OFF_KCG + j * CGP + colb];
                jc0 = fma2(dup2(vc0[j]), kcp, jc0);
                jc1 = fma2(dup2(vc1[j]), kcp, jc1);
            }
            #pragma unroll
            for (int q = 0; q < 16; ++q) {
                ull kbp = *(const ull*)&sm[OFF_KBCG + q * Dn + colb];
                jc0 = fma2(dup2(-c0a[q]), kbp, jc0);
                jc1 = fma2(dup2(-c1a[q]), kbp, jc1);
            }
            float2 d0 = unpack2(jd0), d1 = unpack2(jd1);
            float2 g0 = unpack2(jc0), g1 = unpack2(jc1);
            float jdv[4] = {d0.x, d0.y, d1.x, d1.y};
            float jcv[4] = {g0.x, g0.y, g1.x, g1.y};
            #pragma unroll
            for (int e = 0; e < 4; ++e) {
                float a = clip50(jdv[e] * scale);
                float g = clip50(jcv[e] * scale);
                dd  = fmaf(a, a, dd);
                ccv = fmaf(g, g, ccv);
                dc2 = fmaf(a, g, dc2);
            }
        }
    }
    float cons = 0.f;
    #pragma unroll
    for (int i = 0; i < 8; ++i) {
        float dif = sm[OFF_OUT + tid * 8 + i] - sm[OFF_OCG + tid * 8 + i];
        cons = fmaf(dif, dif, cons);
    }

    #pragma unroll
    for (int o = 16; o > 0; o >>= 1) {
        dd   += __shfl_xor_sync(0xffffffffu, dd,   o);
        ccv  += __shfl_xor_sync(0xffffffffu, ccv,  o);
        dc2  += __shfl_xor_sync(0xffffffffu, dc2,  o);
        cons += __shfl_xor_sync(0xffffffffu, cons, o);
    }
    if (lane == 0) {
        sm[OFF_RED + wid * 4 + 0] = dd;
        sm[OFF_RED + wid * 4 + 1] = ccv;
        sm[OFF_RED + wid * 4 + 2] = dc2;
        sm[OFF_RED + wid * 4 + 3] = cons;
    }
    __syncthreads();
    if (tid == 0) {
        float DD = 0.f, CC = 0.f, DC = 0.f, CO = 0.f;
        #pragma unroll
        for (int w8 = 0; w8 < 8; ++w8) {
            DD += sm[OFF_RED + w8 * 4 + 0];
            CC += sm[OFF_RED + w8 * 4 + 1];
            DC += sm[OFF_RED + w8 * 4 + 2];
            CO += sm[OFF_RED + w8 * 4 + 3];
        }
        float cosv = DC / (sqrtf(DD) * sqrtf(CC) + 1e-8f);
        g_losses[b] = (1.0f - cosv) + CO * (1.0f / (float)(Qn * Dn));
    }
}

__global__ void fml_reduce(float* out) {
    int lane = threadIdx.x;
    float a = 0.f;
    #pragma unroll
    for (int i = 0; i < 8; ++i) a += g_losses[lane * 8 + i];
    #pragma unroll
    for (int o = 16; o > 0; o >>= 1) a += __shfl_xor_sync(0xffffffffu, a, o);
    if (lane == 0) out[0] = a * (1.0f / (float)Bn);
}

extern "C" void kernel_launch(void* const* d_in, const int* in_sizes, int n_in,
                              void* d_out, int out_size)
{
    const float* q   = (const float*)d_in[0];
    const float* k   = (const float*)d_in[1];
    const float* v   = (const float*)d_in[2];
    const float* kcg = (const float*)d_in[3];
    const float* vcg = (const float*)d_in[4];

    cudaFuncSetAttribute(fml_kernel, cudaFuncAttributeMaxDynamicSharedMemorySize,
                         SMEM_FLOATS * (int)sizeof(float));
    fml_kernel<<<Bn, NT, SMEM_FLOATS * sizeof(float)>>>(q, k, v, kcg, vcg);
    fml_reduce<<<1, 32>>>((float*)d_out);
}

// round 8
// speedup vs baseline: 1.5769x; 1.5769x over previous
#include <cuda_runtime.h>
#include <cuda_fp16.h>
#include <cstdint>

#define Bn 256
#define Qn 16
#define Sn 512
#define Mn 8
#define Dn 128
#define NT 256
#define TILE 64
#define NCHUNK 8
#define PPITCH 520
#define CGP 132

typedef unsigned long long ull;

// ---- shared memory layout (float offsets) ----
#define OFF_QT   0          // qT[128][16]
#define OFF_P    2048       // p[16][520]
#define OFF_W    10368      // w[512]
#define OFF_OUT  10880      // out [q][128]
#define OFF_KBAR 12928      // kbar [q][128]
#define OFF_OCG  14976      // cg out [q][128]
#define OFF_KBCG 17024      // cg kbar [q][128]
#define OFF_KCG  19072      // kcg[8][132]
#define OFF_VCG  20128      // vcg[8][132]
#define OFF_PCG  21184      // p_cg[16][8]
#define OFF_WCG  21312      // w_cg[8]
#define OFF_RED  21320      // 8 warps * 4
#define OFF_K32  21376      // fp32 stage [64][129] = 8256 floats -> ends 29632
// fp16 tiles [128 d][64 s] = 4096 floats each, 128B rows, swizzled
#define OFF_VH   29696
#define OFF_VL   33792
#define OFF_KH   37888
#define OFF_KL   41984
#define OFF_WKH  46080
// (WKL tile dropped — J1 is 2-combo now; region 50176 unused)
#define OFF_PH   54272      // p fp16 [16 q][64 s] = 512 floats
#define OFF_PL   54784
#define SMEM_FLOATS 55296   // 221184 bytes

__device__ float g_losses[Bn];

__device__ __forceinline__ float clip50(float x) {
    return fminf(fmaxf(x, -50.0f), 50.0f);
}
__device__ __forceinline__ ull dup2(float x) {
    ull r; asm("mov.b64 %0, {%1, %1};" : "=l"(r) : "f"(x)); return r;
}
__device__ __forceinline__ ull fma2(ull a, ull b, ull c) {
    ull d; asm("fma.rn.f32x2 %0, %1, %2, %3;" : "=l"(d) : "l"(a), "l"(b), "l"(c)); return d;
}
__device__ __forceinline__ float2 unpack2(ull p) {
    float2 f; asm("mov.b64 {%0, %1}, %2;" : "=f"(f.x), "=f"(f.y) : "l"(p)); return f;
}
__device__ __forceinline__ uint32_t smem_u32(const void* p) {
    uint32_t a;
    asm("{ .reg .u64 t; cvta.to.shared.u64 t, %1; cvt.u32.u64 %0, t; }" : "=r"(a) : "l"(p));
    return a;
}
// split (f0,f1) -> fp16x2 hi (f0 in low half) + fp16x2 residual lo
__device__ __forceinline__ void split2h(float f0, float f1, uint32_t& hi, uint32_t& lo) {
    __half2 h = __floats2half2_rn(f0, f1);
    float2 hf = __half22float2(h);
    __half2 l = __floats2half2_rn(f0 - hf.x, f1 - hf.y);
    hi = *(uint32_t*)&h;
    lo = *(uint32_t*)&l;
}
__device__ __forceinline__ uint32_t cvt2h(float f0, float f1) {
    __half2 h = __floats2half2_rn(f0, f1);
    return *(uint32_t*)&h;
}
__device__ __forceinline__ uint32_t swz(uint32_t off) { return off ^ ((off >> 3) & 0x70); }

__device__ __forceinline__ void ldsm4(uint32_t& r0, uint32_t& r1, uint32_t& r2, uint32_t& r3, uint32_t a) {
    asm volatile("ldmatrix.sync.aligned.m8n8.x4.shared.b16 {%0,%1,%2,%3}, [%4];"
                 : "=r"(r0), "=r"(r1), "=r"(r2), "=r"(r3) : "r"(a));
}
__device__ __forceinline__ void mma16816(float* d, const uint32_t* a, uint32_t b0, uint32_t b1) {
    asm volatile("mma.sync.aligned.m16n8k16.row.col.f32.f16.f16.f32 "
                 "{%0,%1,%2,%3}, {%4,%5,%6,%7}, {%8,%9}, {%0,%1,%2,%3};"
                 : "+f"(d[0]), "+f"(d[1]), "+f"(d[2]), "+f"(d[3])
                 : "r"(a[0]), "r"(a[1]), "r"(a[2]), "r"(a[3]), "r"(b0), "r"(b1));
}

__global__ void __launch_bounds__(NT, 1)
fml_kernel(const float* __restrict__ gq, const float* __restrict__ gk,
           const float* __restrict__ gv, const float* __restrict__ gkcg,
           const float* __restrict__ gvcg)
{
    extern __shared__ float sm[];
    char* smc = (char*)sm;
    const int b   = blockIdx.x;
    const int tid = threadIdx.x;
    const int wid = tid >> 5, lane = tid & 31;
    const float scale = 0.088388347648318447f;
    const uint32_t smb = smem_u32(sm);

    // ---- load qT [d][16] and cg tensors ----
    const float* qb = gq + (size_t)b * Qn * Dn;
    for (int i = tid; i < Qn * Dn; i += NT) {
        int qq = i >> 7, d = i & 127;
        sm[OFF_QT + d * 16 + qq] = qb[i];
    }
    const float* kcb = gkcg + (size_t)b * Mn * Dn;
    const float* vcb = gvcg + (size_t)b * Mn * Dn;
    for (int i = tid; i < Mn * Dn; i += NT) {
        int j = i >> 7, d = i & 127;
        sm[OFF_KCG + j * CGP + d] = kcb[i];
        sm[OFF_VCG + j * CGP + d] = vcb[i];
    }
    __syncthreads();

    // ---- cg scores / softmax / w_cg / out / kbar (exact SIMT) ----
    if (tid < Qn * Mn) {
        int qq = tid >> 3, j = tid & 7;
        float acc = 0.f;
        #pragma unroll 8
        for (int d = 0; d < Dn; ++d)
            acc = fmaf(sm[OFF_QT + d * 16 + qq], sm[OFF_KCG + j * CGP + d], acc);
        sm[OFF_PCG + qq * Mn + j] = acc * scale;
    }
    __syncthreads();
    if (tid < Qn) {
        float m = -1e30f;
        #pragma unroll
        for (int j = 0; j < Mn; ++j) m = fmaxf(m, sm[OFF_PCG + tid * Mn + j]);
        float ss = 0.f;
        #pragma unroll
        for (int j = 0; j < Mn; ++j) {
            float e = __expf(sm[OFF_PCG + tid * Mn + j] - m);
            sm[OFF_PCG + tid * Mn + j] = e; ss += e;
        }
        float inv = 1.f / ss;
        #pragma unroll
        for (int j = 0; j < Mn; ++j) sm[OFF_PCG + tid * Mn + j] *= inv;
    }
    __syncthreads();
    if (tid < Mn) {
        float a = 0.f;
        #pragma unroll
        for (int qq = 0; qq < Qn; ++qq) a += sm[OFF_PCG + qq * Mn + tid];
        sm[OFF_WCG + tid] = a;
    }
    {
        int qq = tid >> 4, dblk = tid & 15;
        ull o2[4], kb2[4];
        #pragma unroll
        for (int i = 0; i < 4; ++i) { o2[i] = 0ull; kb2[i] = 0ull; }
        #pragma unroll
        for (int j = 0; j < Mn; ++j) {
            ull pc2 = dup2(sm[OFF_PCG + qq * Mn + j]);
            ulonglong2 vA = *(const ulonglong2*)&sm[OFF_VCG + j * CGP + dblk * 8];
            ulonglong2 vB = *(const ulonglong2*)&sm[OFF_VCG + j * CGP + dblk * 8 + 4];
            ulonglong2 kA = *(const ulonglong2*)&sm[OFF_KCG + j * CGP + dblk * 8];
            ulonglong2 kB = *(const ulonglong2*)&sm[OFF_KCG + j * CGP + dblk * 8 + 4];
            o2[0]  = fma2(pc2, vA.x, o2[0]);  o2[1]  = fma2(pc2, vA.y, o2[1]);
            o2[2]  = fma2(pc2, vB.x, o2[2]);  o2[3]  = fma2(pc2, vB.y, o2[3]);
            kb2[0] = fma2(pc2, kA.x, kb2[0]); kb2[1] = fma2(pc2, kA.y, kb2[1]);
            kb2[2] = fma2(pc2, kB.x, kb2[2]); kb2[3] = fma2(pc2, kB.y, kb2[3]);
        }
        *(ulonglong2*)&sm[OFF_OCG  + qq * Dn + dblk * 8]     = make_ulonglong2(o2[0], o2[1]);
        *(ulonglong2*)&sm[OFF_OCG  + qq * Dn + dblk * 8 + 4] = make_ulonglong2(o2[2], o2[3]);
        *(ulonglong2*)&sm[OFF_KBCG + qq * Dn + dblk * 8]     = make_ulonglong2(kb2[0], kb2[1]);
        *(ulonglong2*)&sm[OFF_KBCG + qq * Dn + dblk * 8 + 4] = make_ulonglong2(kb2[2], kb2[3]);
    }

    // ---- dense scores (fp32 SIMT, exact) ----
    const float* kbase = gk + (size_t)b * Sn * Dn;
    const float* vbase = gv + (size_t)b * Sn * Dn;
    const int qg = tid >> 6;
    const int sl = tid & 63;
    for (int t = 0; t < NCHUNK; ++t) {
        __syncthreads();
        const float4* kg4 = (const float4*)(kbase + (size_t)t * TILE * Dn);
        #pragma unroll
        for (int it = 0; it < 8; ++it) {
            int fidx = tid + it * NT;
            int row = fidx >> 5, c4 = fidx & 31;
            float4 val = kg4[fidx];
            float* dst = &sm[OFF_K32 + row * 129 + c4 * 4];
            dst[0] = val.x; dst[1] = val.y; dst[2] = val.z; dst[3] = val.w;
        }
        __syncthreads();
        ull a01 = 0ull, a23 = 0ull;
        #pragma unroll 8
        for (int d = 0; d < Dn; ++d) {
            ull kv2 = dup2(sm[OFF_K32 + sl * 129 + d]);
            ulonglong2 q2 = *(const ulonglong2*)&sm[OFF_QT + d * 16 + qg * 4];
            a01 = fma2(q2.x, kv2, a01);
            a23 = fma2(q2.y, kv2, a23);
        }
        float2 f01 = unpack2(a01), f23 = unpack2(a23);
        int scol = t * TILE + sl;
        sm[OFF_P + (qg * 4 + 0) * PPITCH + scol] = f01.x * scale;
        sm[OFF_P + (qg * 4 + 1) * PPITCH + scol] = f01.y * scale;
        sm[OFF_P + (qg * 4 + 2) * PPITCH + scol] = f23.x * scale;
        sm[OFF_P + (qg * 4 + 3) * PPITCH + scol] = f23.y * scale;
    }
    __syncthreads();

    // ---- softmax rows + w ----
    #pragma unroll
    for (int r = 0; r < 2; ++r) {
        int qq = wid + r * 8;
        float* row = &sm[OFF_P + qq * PPITCH];
        float m = -1e30f;
        #pragma unroll
        for (int i = 0; i < 16; ++i) m = fmaxf(m, row[lane + 32 * i]);
        #pragma unroll
        for (int o = 16; o > 0; o >>= 1) m = fmaxf(m, __shfl_xor_sync(0xffffffffu, m, o));
        float ss = 0.f;
        float ev[16];
        #pragma unroll
        for (int i = 0; i < 16; ++i) { ev[i] = __expf(row[lane + 32 * i] - m); ss += ev[i]; }
        #pragma unroll
        for (int o = 16; o > 0; o >>= 1) ss += __shfl_xor_sync(0xffffffffu, ss, o);
        float inv = 1.f / ss;
        #pragma unroll
        for (int i = 0; i < 16; ++i) row[lane + 32 * i] = ev[i] * inv;
    }
    __syncthreads();
    for (int s = tid; s < Sn; s += NT) {
        float a = 0.f;
        #pragma unroll
        for (int qq = 0; qq < Qn; ++qq) a += sm[OFF_P + qq * PPITCH + s];
        sm[OFF_W + s] = a;
    }

    // ---- main tensor-core pass ----
    const int grp = lane >> 3, li = lane & 7;
    const int arow = (grp & 1) * 8 + li;     // A fragment rows
    const int akc  = (grp >> 1) * 8;         // A fragment k offset
    const int brow = (grp >> 1) * 8 + li;    // B fragment rows
    const int bkc  = (grp & 1) * 8;          // B fragment k offset
    const int m0   = wid * 16;               // this warp's 16 d-rows

    float accJ[16][4];
    float accO[2][4], accK[2][4];
    #pragma unroll
    for (int nt = 0; nt < 16; ++nt)
        #pragma unroll
        for (int e = 0; e < 4; ++e) accJ[nt][e] = 0.f;
    #pragma unroll
    for (int nt = 0; nt < 2; ++nt)
        #pragma unroll
        for (int e = 0; e < 4; ++e) { accO[nt][e] = 0.f; accK[nt][e] = 0.f; }

    for (int c = 0; c < NCHUNK; ++c) {
        const int s0 = c * TILE;
        __syncthreads();
        // stage K fp32
        {
            const float4* kg4 = (const float4*)(kbase + (size_t)s0 * Dn);
            #pragma unroll
            for (int it = 0; it < 8; ++it) {
                int fidx = tid + it * NT;
                int row = fidx >> 5, c4 = fidx & 31;
                float4 val = kg4[fidx];
                float* dst = &sm[OFF_K32 + row * 129 + c4 * 4];
                dst[0] = val.x; dst[1] = val.y; dst[2] = val.z; dst[3] = val.w;
            }
        }
        __syncthreads();
        // convert K -> KH/KL, wK -> WKH only (transpose [s][d] -> [d][s])
        {
            float w0 = sm[OFF_W + s0 + 2 * lane];
            float w1 = sm[OFF_W + s0 + 2 * lane + 1];
            #pragma unroll
            for (int r = 0; r < 16; ++r) {
                int d = wid * 16 + r;
                float a = sm[OFF_K32 + (2 * lane) * 129 + d];
                float bb = sm[OFF_K32 + (2 * lane + 1) * 129 + d];
                uint32_t sw = swz((uint32_t)(d * 128 + lane * 4));
                uint32_t hi, lo;
                split2h(a, bb, hi, lo);
                *(uint32_t*)(smc + OFF_KH * 4 + sw) = hi;
                *(uint32_t*)(smc + OFF_KL * 4 + sw) = lo;
                *(uint32_t*)(smc + OFF_WKH * 4 + sw) = cvt2h(a * w0, bb * w1);
            }
        }
        __syncthreads();
        // stage V fp32
        {
            const float4* vg4 = (const float4*)(vbase + (size_t)s0 * Dn);
            #pragma unroll
            for (int it = 0; it < 8; ++it) {
                int fidx = tid + it * NT;
                int row = fidx >> 5, c4 = fidx & 31;
                float4 val = vg4[fidx];
                float* dst = &sm[OFF_K32 + row * 129 + c4 * 4];
                dst[0] = val.x; dst[1] = val.y; dst[2] = val.z; dst[3] = val.w;
            }
        }
        __syncthreads();
        // convert V -> VH/VL ; p -> PH/PL
        {
            #pragma unroll
            for (int r = 0; r < 16; ++r) {
                int d = wid * 16 + r;
                float a = sm[OFF_K32 + (2 * lane) * 129 + d];
                float bb = sm[OFF_K32 + (2 * lane + 1) * 129 + d];
                uint32_t sw = swz((uint32_t)(d * 128 + lane * 4));
                uint32_t hi, lo;
                split2h(a, bb, hi, lo);
                *(uint32_t*)(smc + OFF_VH * 4 + sw) = hi;
                *(uint32_t*)(smc + OFF_VL * 4 + sw) = lo;
            }
            #pragma unroll
            for (int rr = 0; rr < 2; ++rr) {
                int qq = wid * 2 + rr;
                float p0 = sm[OFF_P + qq * PPITCH + s0 + 2 * lane];
                float p1 = sm[OFF_P + qq * PPITCH + s0 + 2 * lane + 1];
                uint32_t sw = swz((uint32_t)(qq * 128 + lane * 4));
                uint32_t hi, lo;
                split2h(p0, p1, hi, lo);
                *(uint32_t*)(smc + OFF_PH * 4 + sw) = hi;
                *(uint32_t*)(smc + OFF_PL * 4 + sw) = lo;
            }
        }
        __syncthreads();

        // ---- fragments + MMAs ----
        uint32_t vah[4][4], valo[4][4];
        #pragma unroll
        for (int k = 0; k < 4; ++k) {
            uint32_t addr = swz((uint32_t)((m0 + arow) * 128 + (k * 16 + akc) * 2));
            ldsm4(vah[k][0], vah[k][1], vah[k][2], vah[k][3], smb + OFF_VH * 4 + addr);
            ldsm4(valo[k][0], valo[k][1], valo[k][2], valo[k][3], smb + OFF_VL * 4 + addr);
        }
        // out / kbar (3-combo, exact to ~2^-22)
        #pragma unroll
        for (int k = 0; k < 4; ++k) {
            uint32_t ph[4], pl[4], kah[4], kal[4];
            uint32_t pa = swz((uint32_t)(brow * 128 + (k * 16 + bkc) * 2));
            ldsm4(ph[0], ph[1], ph[2], ph[3], smb + OFF_PH * 4 + pa);
            ldsm4(pl[0], pl[1], pl[2], pl[3], smb + OFF_PL * 4 + pa);
            uint32_t ka = swz((uint32_t)((m0 + arow) * 128 + (k * 16 + akc) * 2));
            ldsm4(kah[0], kah[1], kah[2], kah[3], smb + OFF_KH * 4 + ka);
            ldsm4(kal[0], kal[1], kal[2], kal[3], smb + OFF_KL * 4 + ka);
            mma16816(accO[0], vah[k], ph[0], ph[1]);
            mma16816(accO[0], vah[k], pl[0], pl[1]);
            mma16816(accO[0], valo[k], ph[0], ph[1]);
            mma16816(accO[1], vah[k], ph[2], ph[3]);
            mma16816(accO[1], vah[k], pl[2], pl[3]);
            mma16816(accO[1], valo[k], ph[2], ph[3]);
            mma16816(accK[0], kah, ph[0], ph[1]);
            mma16816(accK[0], kah, pl[0], pl[1]);
            mma16816(accK[0], kal, ph[0], ph[1]);
            mma16816(accK[1], kah, ph[2], ph[3]);
            mma16816(accK[1], kah, pl[2], pl[3]);
            mma16816(accK[1], kal, ph[2], ph[3]);
        }
        // J1 (2-combo: Vh*Wh + Vl*Wh; Vh*Wl dropped)
        #pragma unroll
        for (int k = 0; k < 4; ++k) {
            #pragma unroll
            for (int np = 0; np < 8; ++np) {
                uint32_t bh[4];
                uint32_t ba = swz((uint32_t)((np * 16 + brow) * 128 + (k * 16 + bkc) * 2));
                ldsm4(bh[0], bh[1], bh[2], bh[3], smb + OFF_WKH * 4 + ba);
                mma16816(accJ[np * 2], vah[k], bh[0], bh[1]);
                mma16816(accJ[np * 2], valo[k], bh[0], bh[1]);
                mma16816(accJ[np * 2 + 1], vah[k], bh[2], bh[3]);
                mma16816(accJ[np * 2 + 1], valo[k], bh[2], bh[3]);
            }
        }
    }
    __syncthreads();

    // ---- write out^T / kbar^T to smem as [q][dv] ----
    {
        int r = lane >> 2, cc2 = (lane & 3) * 2;
        #pragma unroll
        for (int nt = 0; nt < 2; ++nt) {
            int qq = nt * 8 + cc2;
            sm[OFF_OUT  + qq * Dn + m0 + r]           = accO[nt][0];
            sm[OFF_OUT  + (qq + 1) * Dn + m0 + r]     = accO[nt][1];
            sm[OFF_OUT  + qq * Dn + m0 + r + 8]       = accO[nt][2];
            sm[OFF_OUT  + (qq + 1) * Dn + m0 + r + 8] = accO[nt][3];
            sm[OFF_KBAR + qq * Dn + m0 + r]           = accK[nt][0];
            sm[OFF_KBAR + (qq + 1) * Dn + m0 + r]     = accK[nt][1];
            sm[OFF_KBAR + qq * Dn + m0 + r + 8]       = accK[nt][2];
            sm[OFF_KBAR + (qq + 1) * Dn + m0 + r + 8] = accK[nt][3];
        }
    }
    __syncthreads();

    // ---- epilogue: J2 + cg jacobian + clip + cosine ----
    const int r = lane >> 2, cc2 = (lane & 3) * 2;
    float o0a[16], o1a[16], c0a[16], c1a[16], vc0[8], vc1[8];
    #pragma unroll
    for (int q = 0; q < 16; ++q) {
        o0a[q] = sm[OFF_OUT + q * Dn + m0 + r];
        o1a[q] = sm[OFF_OUT + q * Dn + m0 + r + 8];
        c0a[q] = sm[OFF_OCG + q * Dn + m0 + r];
        c1a[q] = sm[OFF_OCG + q * Dn + m0 + r + 8];
    }
    #pragma unroll
    for (int j = 0; j < 8; ++j) {
        float wc = sm[OFF_WCG + j];
        vc0[j] = wc * sm[OFF_VCG + j * CGP + m0 + r];
        vc1[j] = wc * sm[OFF_VCG + j * CGP + m0 + r + 8];
    }

    float dd = 0.f, ccv = 0.f, dc = 0.f;
    #pragma unroll
    for (int nt = 0; nt < 16; ++nt) {
        ull jd0, jd1, jc0, jc1;
        asm("mov.b64 %0, {%1, %2};" : "=l"(jd0) : "f"(accJ[nt][0]), "f"(accJ[nt][1]));
        asm("mov.b64 %0, {%1, %2};" : "=l"(jd1) : "f"(accJ[nt][2]), "f"(accJ[nt][3]));
        jc0 = 0ull; jc1 = 0ull;
        int colb = nt * 8 + cc2;
        #pragma unroll
        for (int q = 0; q < 16; ++q) {
            ull kbp = *(const ull*)&sm[OFF_KBAR + q * Dn + colb];
            jd0 = fma2(dup2(-o0a[q]), kbp, jd0);
            jd1 = fma2(dup2(-o1a[q]), kbp, jd1);
        }
        #pragma unroll
        for (int j = 0; j < 8; ++j) {
            ull kcp = *(const ull*)&sm[OFF_KCG + j * CGP + colb];
            jc0 = fma2(dup2(vc0[j]), kcp, jc0);
            jc1 = fma2(dup2(vc1[j]), kcp, jc1);
        }
        #pragma unroll
        for (int q = 0; q < 16; ++q) {
            ull kbp = *(const ull*)&sm[OFF_KBCG + q * Dn + colb];
            jc0 = fma2(dup2(-c0a[q]), kbp, jc0);
            jc1 = fma2(dup2(-c1a[q]), kbp, jc1);
        }
        float2 d0 = unpack2(jd0), d1 = unpack2(jd1);
        float2 g0 = unpack2(jc0), g1 = unpack2(jc1);
        float jdv[4] = {d0.x, d0.y, d1.x, d1.y};
        float jcv[4] = {g0.x, g0.y, g1.x, g1.y};
        #pragma unroll
        for (int e = 0; e < 4; ++e) {
            float a = clip50(jdv[e] * scale);
            float g = clip50(jcv[e] * scale);
            dd  = fmaf(a, a, dd);
            ccv = fmaf(g, g, ccv);
            dc  = fmaf(a, g, dc);
        }
    }
    float cons = 0.f;
    #pragma unroll
    for (int i = 0; i < 8; ++i) {
        float dif = sm[OFF_OUT + tid * 8 + i] - sm[OFF_OCG + tid * 8 + i];
        cons = fmaf(dif, dif, cons);
    }

    #pragma unroll
    for (int o = 16; o > 0; o >>= 1) {
        dd   += __shfl_xor_sync(0xffffffffu, dd,   o);
        ccv  += __shfl_xor_sync(0xffffffffu, ccv,  o);
        dc   += __shfl_xor_sync(0xffffffffu, dc,   o);
        cons += __shfl_xor_sync(0xffffffffu, cons, o);
    }
    if (lane == 0) {
        sm[OFF_RED + wid * 4 + 0] = dd;
        sm[OFF_RED + wid * 4 + 1] = ccv;
        sm[OFF_RED + wid * 4 + 2] = dc;
        sm[OFF_RED + wid * 4 + 3] = cons;
    }
    __syncthreads();
    if (tid == 0) {
        float DD = 0.f, CC = 0.f, DC = 0.f, CO = 0.f;
        #pragma unroll
        for (int w8 = 0; w8 < 8; ++w8) {
            DD += sm[OFF_RED + w8 * 4 + 0];
            CC += sm[OFF_RED + w8 * 4 + 1];
            DC += sm[OFF_RED + w8 * 4 + 2];
            CO += sm[OFF_RED + w8 * 4 + 3];
        }
        float cosv = DC / (sqrtf(DD) * sqrtf(CC) + 1e-8f);
        g_losses[b] = (1.0f - cosv) + CO * (1.0f / (float)(Qn * Dn));
    }
}

__global__ void fml_reduce(float* out) {
    int lane = threadIdx.x;
    float a = 0.f;
    #pragma unroll
    for (int i = 0; i < 8; ++i) a += g_losses[lane * 8 + i];
    #pragma unroll
    for (int o = 16; o > 0; o >>= 1) a += __shfl_xor_sync(0xffffffffu, a, o);
    if (lane == 0) out[0] = a * (1.0f / (float)Bn);
}

extern "C" void kernel_launch(void* const* d_in, const int* in_sizes, int n_in,
                              void* d_out, int out_size)
{
    const float* q   = (const float*)d_in[0];
    const float* k   = (const float*)d_in[1];
    const float* v   = (const float*)d_in[2];
    const float* kcg = (const float*)d_in[3];
    const float* vcg = (const float*)d_in[4];

    cudaFuncSetAttribute(fml_kernel, cudaFuncAttributeMaxDynamicSharedMemorySize,
                         SMEM_FLOATS * (int)sizeof(float));
    fml_kernel<<<Bn, NT, SMEM_FLOATS * sizeof(float)>>>(q, k, v, kcg, vcg);
    fml_reduce<<<1, 32>>>((float*)d_out);
}